// round 6
// baseline (speedup 1.0000x reference)
#include <cuda_runtime.h>
#include <cstdint>
#include <cstddef>

#define MTOT 2048
#define NTOT 4096
#define KTOT 4352
#define HDIM 1024
#define XDIM 2304

#define BM 128
#define BN 256
#define BK 64
#define NST 2
#define LDA 68                                 // 64 + 4 pad (floats)
#define ROWB (LDA * 4)                         // 272B row
#define A_FLOATS (BM * LDA)                    // 8704
#define B_FLOATS (BN * LDA)                    // 17408
#define STAGE_FLOATS (A_FLOATS + B_FLOATS)     // 26112
#define BIAS_OFF (NST * STAGE_FLOATS)
#define SMEM_BYTES ((NST * STAGE_FLOATS + 256) * 4)   // 209920
#define KTILES (KTOT / BK)                     // 68

__device__ float g_Z[(size_t)MTOT * KTOT];
__device__ float g_WB[(size_t)NTOT * KTOT];

__device__ __forceinline__ float rna_tf32(float x) {
    uint32_t r;
    asm("cvt.rna.tf32.f32 %0, %1;" : "=r"(r) : "f"(x));
    return __uint_as_float(r);
}

__device__ __forceinline__ void cp16(float* sdst, const float* gsrc) {
    uint32_t s = (uint32_t)__cvta_generic_to_shared(sdst);
    asm volatile("cp.async.cg.shared.global [%0], [%1], 16;" :: "r"(s), "l"(gsrc));
}

__device__ __forceinline__ void ldsm4(uint32_t addr, uint32_t* r) {
    asm volatile("ldmatrix.sync.aligned.m8n8.x4.shared.b16 {%0,%1,%2,%3}, [%4];"
                 : "=r"(r[0]), "=r"(r[1]), "=r"(r[2]), "=r"(r[3]) : "r"(addr));
}

__device__ __forceinline__ float sigm(float v) { return 1.0f / (1.0f + __expf(-v)); }

// ---------------- pre-round kernels ----------------
__global__ __launch_bounds__(256) void round_z(
    const float* __restrict__ x, const float* __restrict__ pt, const float* __restrict__ pl)
{
    int row = blockIdx.y;
    int c4 = blockIdx.x * 256 + threadIdx.x;
    if (c4 >= KTOT / 4) return;
    int col = c4 * 4;
    const float* src; int ld, cc;
    if (col < XDIM)             { src = x;  ld = XDIM; cc = col; }
    else if (col < XDIM + HDIM) { src = pt; ld = HDIM; cc = col - XDIM; }
    else                        { src = pl; ld = HDIM; cc = col - XDIM - HDIM; }
    float4 v = *reinterpret_cast<const float4*>(src + (size_t)row * ld + cc);
    v.x = rna_tf32(v.x); v.y = rna_tf32(v.y); v.z = rna_tf32(v.z); v.w = rna_tf32(v.w);
    *reinterpret_cast<float4*>(g_Z + (size_t)row * KTOT + col) = v;
}

__global__ __launch_bounds__(256) void round_w(
    const float* __restrict__ Wi, const float* __restrict__ Wf,
    const float* __restrict__ Wo, const float* __restrict__ Ws)
{
    int g = blockIdx.y;
    int c4 = blockIdx.x * 256 + threadIdx.x;
    if (c4 >= KTOT / 4) return;
    int n_tile = g >> 8, r = g & 255;
    int h = n_tile * 64 + (r >> 2);
    int gate = r & 3;
    const float* W = (gate == 0) ? Wi : (gate == 1) ? Wf : (gate == 2) ? Wo : Ws;
    int col = c4 * 4;
    float4 v = *reinterpret_cast<const float4*>(W + (size_t)h * KTOT + col);
    v.x = rna_tf32(v.x); v.y = rna_tf32(v.y); v.z = rna_tf32(v.z); v.w = rna_tf32(v.w);
    *reinterpret_cast<float4*>(g_WB + (size_t)g * KTOT + col) = v;
}

__global__ void shim_kernel(void) {}

// ---------------- GEMM + fused LSTM gates ----------------
__global__ __launch_bounds__(256, 1) void gemm_lstm(
    const float* __restrict__ old_state,
    const float* __restrict__ bi, const float* __restrict__ bf,
    const float* __restrict__ bo, const float* __restrict__ bs,
    float* __restrict__ out)
{
    extern __shared__ float smem[];
    const uint32_t smem_u = (uint32_t)__cvta_generic_to_shared(smem);

    const int tid  = threadIdx.x;
    const int lane = tid & 31;
    const int warp = tid >> 5;
    const int wm   = (warp & 1) * 64;
    const int wn   = (warp >> 1) * 64;
    const int m0   = blockIdx.y * BM;
    const int n_tile = blockIdx.x;
    const int h0   = n_tile * 64;

    const float* gA = g_Z  + (size_t)m0 * KTOT;
    const float* gB = g_WB + (size_t)(n_tile * BN) * KTOT;

    float* bias_sm = smem + BIAS_OFF;
    {
        int hl = tid >> 2, gate = tid & 3;
        const float* b = (gate == 0) ? bi : (gate == 1) ? bf : (gate == 2) ? bo : bs;
        bias_sm[tid] = b[h0 + hl];
    }

    // loader coords: 16 chunks (16B) per 64-float row; 256 threads = 16 rows/iter
    const int lrow = tid >> 4;
    const int lch  = (tid & 15) << 2;

    // LDSM per-lane offsets
    const uint32_t aOff = (uint32_t)((wm + (lane & 7) + ((lane >> 3) & 1) * 8) * ROWB
                                     + (lane >> 4) * 16);
    const uint32_t bOff = (uint32_t)(A_FLOATS * 4
                                     + (wn + (lane & 7) + ((lane >> 4) & 1) * 8) * ROWB
                                     + ((lane >> 3) & 1) * 16);

    float acc[4][8][4];
#pragma unroll
    for (int t = 0; t < 4; t++)
#pragma unroll
        for (int u = 0; u < 8; u++)
#pragma unroll
            for (int v = 0; v < 4; v++) acc[t][u][v] = 0.f;

    auto load_stage = [&](int kt) {
        float* As = smem + (kt & 1) * STAGE_FLOATS;
        float* Bs = As + A_FLOATS;
        const int k0 = kt * BK;
#pragma unroll
        for (int i = 0; i < 8; i++) {
            int r = lrow + i * 16;
            cp16(&As[r * LDA + lch], gA + (size_t)r * KTOT + k0 + lch);
        }
#pragma unroll
        for (int i = 0; i < 16; i++) {
            int r = lrow + i * 16;
            cp16(&Bs[r * LDA + lch], gB + (size_t)r * KTOT + k0 + lch);
        }
    };

    load_stage(0);
    asm volatile("cp.async.commit_group;");

    uint32_t afr[2][4][4], bfr[2][4][4];

    for (int kt = 0; kt < KTILES; kt++) {
        asm volatile("cp.async.wait_group 0;");
        __syncthreads();

        // start next-stage loads immediately (fills while we compute this tile)
        if (kt + 1 < KTILES) load_stage(kt + 1);
        asm volatile("cp.async.commit_group;");

        const uint32_t stage = smem_u + (uint32_t)((kt & 1) * STAGE_FLOATS * 4);
        const uint32_t aBase = stage + aOff;
        const uint32_t bBase = stage + bOff;

        // prefetch fragments for ks=0
#pragma unroll
        for (int t = 0; t < 4; t++) ldsm4(aBase + t * (16 * ROWB), afr[0][t]);
#pragma unroll
        for (int j = 0; j < 4; j++) ldsm4(bBase + j * (16 * ROWB), bfr[0][j]);

#pragma unroll
        for (int ks = 0; ks < 8; ks++) {
            const int cur = ks & 1, nxt = cur ^ 1;
            if (ks < 7) {
#pragma unroll
                for (int t = 0; t < 4; t++)
                    ldsm4(aBase + (ks + 1) * 32 + t * (16 * ROWB), afr[nxt][t]);
#pragma unroll
                for (int j = 0; j < 4; j++)
                    ldsm4(bBase + (ks + 1) * 32 + j * (16 * ROWB), bfr[nxt][j]);
            }
#pragma unroll
            for (int t = 0; t < 4; t++)
#pragma unroll
                for (int j = 0; j < 4; j++) {
                    asm volatile(
                        "mma.sync.aligned.m16n8k8.row.col.f32.tf32.tf32.f32 "
                        "{%0,%1,%2,%3},{%4,%5,%6,%7},{%8,%9},{%0,%1,%2,%3};"
                        : "+f"(acc[t][2*j][0]), "+f"(acc[t][2*j][1]),
                          "+f"(acc[t][2*j][2]), "+f"(acc[t][2*j][3])
                        : "r"(afr[cur][t][0]), "r"(afr[cur][t][1]),
                          "r"(afr[cur][t][2]), "r"(afr[cur][t][3]),
                          "r"(bfr[cur][j][0]), "r"(bfr[cur][j][1]));
                    asm volatile(
                        "mma.sync.aligned.m16n8k8.row.col.f32.tf32.tf32.f32 "
                        "{%0,%1,%2,%3},{%4,%5,%6,%7},{%8,%9},{%0,%1,%2,%3};"
                        : "+f"(acc[t][2*j+1][0]), "+f"(acc[t][2*j+1][1]),
                          "+f"(acc[t][2*j+1][2]), "+f"(acc[t][2*j+1][3])
                        : "r"(afr[cur][t][0]), "r"(afr[cur][t][1]),
                          "r"(afr[cur][t][2]), "r"(afr[cur][t][3]),
                          "r"(bfr[cur][j][2]), "r"(bfr[cur][j][3]));
                }
        }
    }

    // ---- fused LSTM gate epilogue ----
    const int hadj = (lane & 3) >> 1;
    const int row_sel = (lane & 1) << 3;
#pragma unroll
    for (int t = 0; t < 4; t++) {
        int r_out = m0 + wm + t * 16 + (lane >> 2) + row_sel;
        const float* oldr = old_state + (size_t)r_out * HDIM + h0;
        float*       outr = out       + (size_t)r_out * HDIM + h0;
#pragma unroll
        for (int u = 0; u < 8; u++) {
            float v0 = acc[t][u][0], v1 = acc[t][u][1];
            float v2 = acc[t][u][2], v3 = acc[t][u][3];
            float t0 = (lane & 1) ? v0 : v2;
            float t1 = (lane & 1) ? v1 : v3;
            float e0 = __shfl_xor_sync(0xffffffffu, t0, 1);
            float e1 = __shfl_xor_sync(0xffffffffu, t1, 1);
            float gi, gf, go, gs;
            if (lane & 1) { gi = e0; gf = e1; go = v2; gs = v3; }
            else          { gi = v0; gf = v1; go = e0; gs = e1; }
            int hl = ((wn + u * 8) >> 2) + hadj;
            gi += bias_sm[hl * 4 + 0];
            gf += bias_sm[hl * 4 + 1];
            go += bias_sm[hl * 4 + 2];
            gs += bias_sm[hl * 4 + 3];
            float c  = __ldg(oldr + hl);
            float ns = sigm(gf) * c + sigm(gi) * tanhf(gs);
            outr[hl] = sigm(go) * tanhf(ns);
        }
    }
}

extern "C" void kernel_launch(void* const* d_in, const int* in_sizes, int n_in,
                              void* d_out, int out_size)
{
    const float* x  = (const float*)d_in[0];
    const float* pt = (const float*)d_in[1];
    const float* pl = (const float*)d_in[2];
    const float* os = (const float*)d_in[3];
    const float* Wi = (const float*)d_in[4];
    const float* bi = (const float*)d_in[5];
    const float* Wf = (const float*)d_in[6];
    const float* bf = (const float*)d_in[7];
    const float* Wo = (const float*)d_in[8];
    const float* bo = (const float*)d_in[9];
    const float* Ws = (const float*)d_in[10];
    const float* bs = (const float*)d_in[11];
    float* out = (float*)d_out;

    cudaFuncSetAttribute(gemm_lstm, cudaFuncAttributeMaxDynamicSharedMemorySize, SMEM_BYTES);

    round_z<<<dim3(5, MTOT), 256>>>(x, pt, pl);
    round_w<<<dim3(5, NTOT), 256>>>(Wi, Wf, Wo, Ws);
    shim_kernel<<<1, 32>>>();
    gemm_lstm<<<dim3(NTOT / BN, MTOT / BM), 256, SMEM_BYTES>>>(os, bi, bf, bo, bs, out);
}

// round 7
// speedup vs baseline: 1.0178x; 1.0178x over previous
#include <cuda_runtime.h>
#include <cstdint>
#include <cstddef>

#define MTOT 2048
#define NTOT 4096
#define KTOT 4352
#define HDIM 1024
#define XDIM 2304

#define BM 128
#define BN 128
#define BK 32
#define NST 3
#define LDA 36
#define ROWB (LDA * 4)                          // 144B row
#define A_FLOATS (BM * LDA)                     // 4608
#define B_FLOATS (BN * LDA)                     // 4608
#define STAGE_FLOATS (A_FLOATS + B_FLOATS)      // 9216
#define BIAS_OFF (NST * STAGE_FLOATS)
#define SMEM_BYTES ((NST * STAGE_FLOATS + 128) * 4)   // 111104
#define KTILES (KTOT / BK)                      // 136

__device__ float g_Z[(size_t)MTOT * KTOT];
__device__ float g_WB[(size_t)NTOT * KTOT];

__device__ __forceinline__ float rna_tf32(float x) {
    uint32_t r;
    asm("cvt.rna.tf32.f32 %0, %1;" : "=r"(r) : "f"(x));
    return __uint_as_float(r);
}

__device__ __forceinline__ void cp16(float* sdst, const float* gsrc) {
    uint32_t s = (uint32_t)__cvta_generic_to_shared(sdst);
    asm volatile("cp.async.cg.shared.global [%0], [%1], 16;" :: "r"(s), "l"(gsrc));
}

__device__ __forceinline__ void ldsm4(uint32_t addr, uint32_t* r) {
    asm volatile("ldmatrix.sync.aligned.m8n8.x4.shared.b16 {%0,%1,%2,%3}, [%4];"
                 : "=r"(r[0]), "=r"(r[1]), "=r"(r[2]), "=r"(r[3]) : "r"(addr));
}

__device__ __forceinline__ float sigm(float v) { return 1.0f / (1.0f + __expf(-v)); }

// ---------------- pre-round kernels ----------------
__global__ __launch_bounds__(256) void round_z(
    const float* __restrict__ x, const float* __restrict__ pt, const float* __restrict__ pl)
{
    int row = blockIdx.y;
    int c4 = blockIdx.x * 256 + threadIdx.x;
    if (c4 >= KTOT / 4) return;
    int col = c4 * 4;
    const float* src; int ld, cc;
    if (col < XDIM)             { src = x;  ld = XDIM; cc = col; }
    else if (col < XDIM + HDIM) { src = pt; ld = HDIM; cc = col - XDIM; }
    else                        { src = pl; ld = HDIM; cc = col - XDIM - HDIM; }
    float4 v = *reinterpret_cast<const float4*>(src + (size_t)row * ld + cc);
    v.x = rna_tf32(v.x); v.y = rna_tf32(v.y); v.z = rna_tf32(v.z); v.w = rna_tf32(v.w);
    *reinterpret_cast<float4*>(g_Z + (size_t)row * KTOT + col) = v;
}

// global gate interleave: row g = h*4 + gate
__global__ __launch_bounds__(256) void round_w(
    const float* __restrict__ Wi, const float* __restrict__ Wf,
    const float* __restrict__ Wo, const float* __restrict__ Ws)
{
    int g = blockIdx.y;
    int c4 = blockIdx.x * 256 + threadIdx.x;
    if (c4 >= KTOT / 4) return;
    int h = g >> 2;
    int gate = g & 3;
    const float* W = (gate == 0) ? Wi : (gate == 1) ? Wf : (gate == 2) ? Wo : Ws;
    int col = c4 * 4;
    float4 v = *reinterpret_cast<const float4*>(W + (size_t)h * KTOT + col);
    v.x = rna_tf32(v.x); v.y = rna_tf32(v.y); v.z = rna_tf32(v.z); v.w = rna_tf32(v.w);
    *reinterpret_cast<float4*>(g_WB + (size_t)g * KTOT + col) = v;
}

__global__ void shim_kernel(void) {}

// ---------------- GEMM + fused LSTM gates: 128x128 CTA, 2 CTAs/SM ----------------
__global__ __launch_bounds__(256, 2) void gemm_lstm(
    const float* __restrict__ old_state,
    const float* __restrict__ bi, const float* __restrict__ bf,
    const float* __restrict__ bo, const float* __restrict__ bs,
    float* __restrict__ out)
{
    extern __shared__ float smem[];
    const uint32_t smem_u = (uint32_t)__cvta_generic_to_shared(smem);

    const int tid  = threadIdx.x;
    const int lane = tid & 31;
    const int warp = tid >> 5;
    const int wm   = (warp & 1) * 64;        // 2 warps in M (64 each)
    const int wn   = (warp >> 1) * 32;       // 4 warps in N (32 each)
    const int m0   = blockIdx.y * BM;
    const int n_tile = blockIdx.x;
    const int h0   = n_tile * 32;            // 32 hidden units per CTA

    const float* gA = g_Z  + (size_t)m0 * KTOT;
    const float* gB = g_WB + (size_t)(n_tile * BN) * KTOT;

    float* bias_sm = smem + BIAS_OFF;        // [32][4]
    if (tid < 128) {
        int hl = tid >> 2, gate = tid & 3;
        const float* b = (gate == 0) ? bi : (gate == 1) ? bf : (gate == 2) ? bo : bs;
        bias_sm[tid] = b[h0 + hl];
    }

    const int lr = tid >> 3;                 // 0..31
    const int lc = (tid & 7) << 2;

    // LDSM per-lane offsets
    const uint32_t aOff = (uint32_t)((wm + (lane & 7) + ((lane >> 3) & 1) * 8) * ROWB
                                     + (lane >> 4) * 16);
    const uint32_t bOff = (uint32_t)(A_FLOATS * 4
                                     + (wn + (lane & 7) + ((lane >> 4) & 1) * 8) * ROWB
                                     + ((lane >> 3) & 1) * 16);

    float acc[4][4][4];
#pragma unroll
    for (int t = 0; t < 4; t++)
#pragma unroll
        for (int u = 0; u < 4; u++)
#pragma unroll
            for (int v = 0; v < 4; v++) acc[t][u][v] = 0.f;

    auto load_stage = [&](int kt) {
        float* As = smem + (kt % NST) * STAGE_FLOATS;
        float* Bs = As + A_FLOATS;
        const int k0 = kt * BK;
#pragma unroll
        for (int i = 0; i < 4; i++) {
            int r = lr + i * 32;
            cp16(&As[r * LDA + lc], gA + (size_t)r * KTOT + k0 + lc);
        }
#pragma unroll
        for (int i = 0; i < 4; i++) {
            int r = lr + i * 32;
            cp16(&Bs[r * LDA + lc], gB + (size_t)r * KTOT + k0 + lc);
        }
    };

#pragma unroll
    for (int s = 0; s < NST - 1; s++) {
        load_stage(s);
        asm volatile("cp.async.commit_group;");
    }

    for (int kt = 0; kt < KTILES; kt++) {
        asm volatile("cp.async.wait_group %0;" :: "n"(NST - 2));
        __syncthreads();
        if (kt + NST - 1 < KTILES) load_stage(kt + NST - 1);
        asm volatile("cp.async.commit_group;");

        const uint32_t stage = smem_u + (uint32_t)((kt % NST) * STAGE_FLOATS * 4);
        const uint32_t aBase = stage + aOff;
        const uint32_t bBase = stage + bOff;

#pragma unroll
        for (int ks = 0; ks < 4; ks++) {
            uint32_t a[4][4], b[2][4];
#pragma unroll
            for (int t = 0; t < 4; t++)
                ldsm4(aBase + ks * 32 + t * (16 * ROWB), a[t]);
#pragma unroll
            for (int j = 0; j < 2; j++)
                ldsm4(bBase + ks * 32 + j * (16 * ROWB), b[j]);
#pragma unroll
            for (int t = 0; t < 4; t++)
#pragma unroll
                for (int j = 0; j < 2; j++) {
                    asm volatile(
                        "mma.sync.aligned.m16n8k8.row.col.f32.tf32.tf32.f32 "
                        "{%0,%1,%2,%3},{%4,%5,%6,%7},{%8,%9},{%0,%1,%2,%3};"
                        : "+f"(acc[t][2*j][0]), "+f"(acc[t][2*j][1]),
                          "+f"(acc[t][2*j][2]), "+f"(acc[t][2*j][3])
                        : "r"(a[t][0]), "r"(a[t][1]), "r"(a[t][2]), "r"(a[t][3]),
                          "r"(b[j][0]), "r"(b[j][1]));
                    asm volatile(
                        "mma.sync.aligned.m16n8k8.row.col.f32.tf32.tf32.f32 "
                        "{%0,%1,%2,%3},{%4,%5,%6,%7},{%8,%9},{%0,%1,%2,%3};"
                        : "+f"(acc[t][2*j+1][0]), "+f"(acc[t][2*j+1][1]),
                          "+f"(acc[t][2*j+1][2]), "+f"(acc[t][2*j+1][3])
                        : "r"(a[t][0]), "r"(a[t][1]), "r"(a[t][2]), "r"(a[t][3]),
                          "r"(b[j][2]), "r"(b[j][3]));
                }
        }
    }

    // ---- fused LSTM gate epilogue ----
    const int hadj = (lane & 3) >> 1;
    const int row_sel = (lane & 1) << 3;
#pragma unroll
    for (int t = 0; t < 4; t++) {
        int r_out = m0 + wm + t * 16 + (lane >> 2) + row_sel;
        const float* oldr = old_state + (size_t)r_out * HDIM + h0;
        float*       outr = out       + (size_t)r_out * HDIM + h0;
#pragma unroll
        for (int u = 0; u < 4; u++) {
            float v0 = acc[t][u][0], v1 = acc[t][u][1];
            float v2 = acc[t][u][2], v3 = acc[t][u][3];
            float t0 = (lane & 1) ? v0 : v2;
            float t1 = (lane & 1) ? v1 : v3;
            float e0 = __shfl_xor_sync(0xffffffffu, t0, 1);
            float e1 = __shfl_xor_sync(0xffffffffu, t1, 1);
            float gi, gf, go, gs;
            if (lane & 1) { gi = e0; gf = e1; go = v2; gs = v3; }
            else          { gi = v0; gf = v1; go = e0; gs = e1; }
            int hl = ((wn + u * 8) >> 2) + hadj;
            gi += bias_sm[hl * 4 + 0];
            gf += bias_sm[hl * 4 + 1];
            go += bias_sm[hl * 4 + 2];
            gs += bias_sm[hl * 4 + 3];
            float c  = __ldg(oldr + hl);
            float ns = sigm(gf) * c + sigm(gi) * tanhf(gs);
            outr[hl] = sigm(go) * tanhf(ns);
        }
    }
}

extern "C" void kernel_launch(void* const* d_in, const int* in_sizes, int n_in,
                              void* d_out, int out_size)
{
    const float* x  = (const float*)d_in[0];
    const float* pt = (const float*)d_in[1];
    const float* pl = (const float*)d_in[2];
    const float* os = (const float*)d_in[3];
    const float* Wi = (const float*)d_in[4];
    const float* bi = (const float*)d_in[5];
    const float* Wf = (const float*)d_in[6];
    const float* bf = (const float*)d_in[7];
    const float* Wo = (const float*)d_in[8];
    const float* bo = (const float*)d_in[9];
    const float* Ws = (const float*)d_in[10];
    const float* bs = (const float*)d_in[11];
    float* out = (float*)d_out;

    cudaFuncSetAttribute(gemm_lstm, cudaFuncAttributeMaxDynamicSharedMemorySize, SMEM_BYTES);

    round_z<<<dim3(5, MTOT), 256>>>(x, pt, pl);
    round_w<<<dim3(5, NTOT), 256>>>(Wi, Wf, Wo, Ws);
    shim_kernel<<<1, 32>>>();
    gemm_lstm<<<dim3(NTOT / BN, MTOT / BM), 256, SMEM_BYTES>>>(os, bi, bf, bo, bs, out);
}

// round 8
// speedup vs baseline: 1.2273x; 1.2058x over previous
#include <cuda_runtime.h>
#include <cuda_fp16.h>
#include <cstdint>
#include <cstddef>

#define MTOT 2048
#define NTOT 4096
#define KTOT 4352
#define HDIM 1024
#define XDIM 2304

#define BM 128
#define BN 128
#define BK 64                                   // halves per K-tile
#define NST 3
#define LDA_H 72                                // padded row stride in halves (144B)
#define ROWB 144
#define A_HALF (BM * LDA_H)                     // 9216
#define B_HALF (BN * LDA_H)                     // 9216
#define STAGE_HALF (A_HALF + B_HALF)            // 18432 (36864 B)
#define A_BYTES (BM * ROWB)                     // 18432
#define BIAS_BYTE_OFF (NST * STAGE_HALF * 2)    // 110592
#define SMEM_BYTES (BIAS_BYTE_OFF + 512)        // 111104
#define KTILES (KTOT / BK)                      // 68

__device__ __half g_Z[(size_t)MTOT * KTOT];
__device__ __half g_WB[(size_t)NTOT * KTOT];

__device__ __forceinline__ void cp16(void* sdst, const void* gsrc) {
    uint32_t s = (uint32_t)__cvta_generic_to_shared(sdst);
    asm volatile("cp.async.cg.shared.global [%0], [%1], 16;" :: "r"(s), "l"(gsrc));
}

__device__ __forceinline__ void ldsm4(uint32_t addr, uint32_t* r) {
    asm volatile("ldmatrix.sync.aligned.m8n8.x4.shared.b16 {%0,%1,%2,%3}, [%4];"
                 : "=r"(r[0]), "=r"(r[1]), "=r"(r[2]), "=r"(r[3]) : "r"(addr));
}

__device__ __forceinline__ float sigm(float v) { return 1.0f / (1.0f + __expf(-v)); }

// ---------------- convert kernels ----------------
__global__ __launch_bounds__(256) void conv_z(
    const float* __restrict__ x, const float* __restrict__ pt, const float* __restrict__ pl)
{
    int row = blockIdx.y;
    int c4 = blockIdx.x * 256 + threadIdx.x;
    if (c4 >= KTOT / 4) return;
    int col = c4 * 4;
    const float* src; int ld, cc;
    if (col < XDIM)             { src = x;  ld = XDIM; cc = col; }
    else if (col < XDIM + HDIM) { src = pt; ld = HDIM; cc = col - XDIM; }
    else                        { src = pl; ld = HDIM; cc = col - XDIM - HDIM; }
    float4 v = *reinterpret_cast<const float4*>(src + (size_t)row * ld + cc);
    __half2 h0 = __floats2half2_rn(v.x, v.y);
    __half2 h1 = __floats2half2_rn(v.z, v.w);
    uint2 u;
    u.x = *reinterpret_cast<uint32_t*>(&h0);
    u.y = *reinterpret_cast<uint32_t*>(&h1);
    *reinterpret_cast<uint2*>(g_Z + (size_t)row * KTOT + col) = u;
}

// global gate interleave: row g = h*4 + gate
__global__ __launch_bounds__(256) void conv_w(
    const float* __restrict__ Wi, const float* __restrict__ Wf,
    const float* __restrict__ Wo, const float* __restrict__ Ws)
{
    int g = blockIdx.y;
    int c4 = blockIdx.x * 256 + threadIdx.x;
    if (c4 >= KTOT / 4) return;
    int h = g >> 2;
    int gate = g & 3;
    const float* W = (gate == 0) ? Wi : (gate == 1) ? Wf : (gate == 2) ? Wo : Ws;
    int col = c4 * 4;
    float4 v = *reinterpret_cast<const float4*>(W + (size_t)h * KTOT + col);
    __half2 h0 = __floats2half2_rn(v.x, v.y);
    __half2 h1 = __floats2half2_rn(v.z, v.w);
    uint2 u;
    u.x = *reinterpret_cast<uint32_t*>(&h0);
    u.y = *reinterpret_cast<uint32_t*>(&h1);
    *reinterpret_cast<uint2*>(g_WB + (size_t)g * KTOT + col) = u;
}

__global__ void shim_kernel(void) {}

// ---------------- fp16 GEMM + fused LSTM gates: 128x128 CTA, 2 CTAs/SM ----------------
__global__ __launch_bounds__(256, 2) void gemm_lstm(
    const float* __restrict__ old_state,
    const float* __restrict__ bi, const float* __restrict__ bf,
    const float* __restrict__ bo, const float* __restrict__ bs,
    float* __restrict__ out)
{
    extern __shared__ __align__(16) char smem[];
    const uint32_t smem_u = (uint32_t)__cvta_generic_to_shared(smem);

    const int tid  = threadIdx.x;
    const int lane = tid & 31;
    const int warp = tid >> 5;
    const int wm   = (warp & 1) * 64;        // 2 warps in M
    const int wn   = (warp >> 1) * 32;       // 4 warps in N
    const int m0   = blockIdx.y * BM;
    const int n_tile = blockIdx.x;
    const int h0   = n_tile * 32;

    const __half* gA = g_Z  + (size_t)m0 * KTOT;
    const __half* gB = g_WB + (size_t)(n_tile * BN) * KTOT;

    float* bias_sm = reinterpret_cast<float*>(smem + BIAS_BYTE_OFF);   // [32][4]
    if (tid < 128) {
        int hl = tid >> 2, gate = tid & 3;
        const float* b = (gate == 0) ? bi : (gate == 1) ? bf : (gate == 2) ? bo : bs;
        bias_sm[tid] = b[h0 + hl];
    }

    // loader: rows of 64 halves = 128B = 8 chunks; 256 thr = 32 rows/iter
    const int lr = tid >> 3;                  // 0..31
    const int lcb = (tid & 7) << 4;           // chunk byte offset 0..112

    // LDSM per-lane offsets (quads are 16B = 8 halves)
    const uint32_t aOff = (uint32_t)((wm + (lane & 7) + ((lane >> 3) & 1) * 8) * ROWB
                                     + (lane >> 4) * 16);
    const uint32_t bOff = (uint32_t)(A_BYTES
                                     + (wn + (lane & 7) + ((lane >> 4) & 1) * 8) * ROWB
                                     + ((lane >> 3) & 1) * 16);

    float acc[4][4][4];
#pragma unroll
    for (int t = 0; t < 4; t++)
#pragma unroll
        for (int u = 0; u < 4; u++)
#pragma unroll
            for (int v = 0; v < 4; v++) acc[t][u][v] = 0.f;

    auto load_stage = [&](int kt) {
        char* As = smem + (kt % NST) * (STAGE_HALF * 2);
        char* Bs = As + A_BYTES;
        const int k0 = kt * BK;
#pragma unroll
        for (int i = 0; i < 4; i++) {
            int r = lr + i * 32;
            cp16(As + r * ROWB + lcb, (const char*)(gA + (size_t)r * KTOT + k0) + lcb);
        }
#pragma unroll
        for (int i = 0; i < 4; i++) {
            int r = lr + i * 32;
            cp16(Bs + r * ROWB + lcb, (const char*)(gB + (size_t)r * KTOT + k0) + lcb);
        }
    };

#pragma unroll
    for (int s = 0; s < NST - 1; s++) {
        load_stage(s);
        asm volatile("cp.async.commit_group;");
    }

    for (int kt = 0; kt < KTILES; kt++) {
        asm volatile("cp.async.wait_group %0;" :: "n"(NST - 2));
        __syncthreads();
        if (kt + NST - 1 < KTILES) load_stage(kt + NST - 1);
        asm volatile("cp.async.commit_group;");

        const uint32_t stage = smem_u + (uint32_t)((kt % NST) * (STAGE_HALF * 2));
        const uint32_t aBase = stage + aOff;
        const uint32_t bBase = stage + bOff;

#pragma unroll
        for (int ks = 0; ks < 4; ks++) {      // each ks = k16 (32B)
            uint32_t a[4][4], b[2][4];
#pragma unroll
            for (int t = 0; t < 4; t++)
                ldsm4(aBase + ks * 32 + t * (16 * ROWB), a[t]);
#pragma unroll
            for (int j = 0; j < 2; j++)
                ldsm4(bBase + ks * 32 + j * (16 * ROWB), b[j]);
#pragma unroll
            for (int t = 0; t < 4; t++)
#pragma unroll
                for (int u = 0; u < 4; u++) {
                    const uint32_t b0 = (u & 1) ? b[u >> 1][2] : b[u >> 1][0];
                    const uint32_t b1 = (u & 1) ? b[u >> 1][3] : b[u >> 1][1];
                    asm volatile(
                        "mma.sync.aligned.m16n8k16.row.col.f32.f16.f16.f32 "
                        "{%0,%1,%2,%3},{%4,%5,%6,%7},{%8,%9},{%0,%1,%2,%3};"
                        : "+f"(acc[t][u][0]), "+f"(acc[t][u][1]),
                          "+f"(acc[t][u][2]), "+f"(acc[t][u][3])
                        : "r"(a[t][0]), "r"(a[t][1]), "r"(a[t][2]), "r"(a[t][3]),
                          "r"(b0), "r"(b1));
                }
        }
    }

    // ---- fused LSTM gate epilogue ----
    const int hadj = (lane & 3) >> 1;
    const int row_sel = (lane & 1) << 3;
#pragma unroll
    for (int t = 0; t < 4; t++) {
        int r_out = m0 + wm + t * 16 + (lane >> 2) + row_sel;
        const float* oldr = old_state + (size_t)r_out * HDIM + h0;
        float*       outr = out       + (size_t)r_out * HDIM + h0;
#pragma unroll
        for (int u = 0; u < 4; u++) {
            float v0 = acc[t][u][0], v1 = acc[t][u][1];
            float v2 = acc[t][u][2], v3 = acc[t][u][3];
            float t0 = (lane & 1) ? v0 : v2;
            float t1 = (lane & 1) ? v1 : v3;
            float e0 = __shfl_xor_sync(0xffffffffu, t0, 1);
            float e1 = __shfl_xor_sync(0xffffffffu, t1, 1);
            float gi, gf, go, gs;
            if (lane & 1) { gi = e0; gf = e1; go = v2; gs = v3; }
            else          { gi = v0; gf = v1; go = e0; gs = e1; }
            int hl = ((wn + u * 8) >> 2) + hadj;
            gi += bias_sm[hl * 4 + 0];
            gf += bias_sm[hl * 4 + 1];
            go += bias_sm[hl * 4 + 2];
            gs += bias_sm[hl * 4 + 3];
            float c  = __ldg(oldr + hl);
            float ns = sigm(gf) * c + sigm(gi) * tanhf(gs);
            outr[hl] = sigm(go) * tanhf(ns);
        }
    }
}

extern "C" void kernel_launch(void* const* d_in, const int* in_sizes, int n_in,
                              void* d_out, int out_size)
{
    const float* x  = (const float*)d_in[0];
    const float* pt = (const float*)d_in[1];
    const float* pl = (const float*)d_in[2];
    const float* os = (const float*)d_in[3];
    const float* Wi = (const float*)d_in[4];
    const float* bi = (const float*)d_in[5];
    const float* Wf = (const float*)d_in[6];
    const float* bf = (const float*)d_in[7];
    const float* Wo = (const float*)d_in[8];
    const float* bo = (const float*)d_in[9];
    const float* Ws = (const float*)d_in[10];
    const float* bs = (const float*)d_in[11];
    float* out = (float*)d_out;

    cudaFuncSetAttribute(gemm_lstm, cudaFuncAttributeMaxDynamicSharedMemorySize, SMEM_BYTES);

    conv_z<<<dim3(5, MTOT), 256>>>(x, pt, pl);
    conv_w<<<dim3(5, NTOT), 256>>>(Wi, Wf, Wo, Ws);
    shim_kernel<<<1, 32>>>();
    gemm_lstm<<<dim3(NTOT / BN, MTOT / BM), 256, SMEM_BYTES>>>(os, bi, bf, bo, bs, out);
}

// round 9
// speedup vs baseline: 1.7994x; 1.4662x over previous
#include <cuda_runtime.h>
#include <cuda_fp16.h>
#include <cstdint>
#include <cstddef>

#define MTOT 2048
#define NTOT 4096
#define KTOT 4352
#define HDIM 1024
#define XDIM 2304

#define BM 128
#define BN 256
#define BK 64                                   // halves per K-tile
#define NST 3
#define ROWB 144                                // 128B data + 16B pad
#define A_BYTES (BM * ROWB)                     // 18432
#define B_BYTES (BN * ROWB)                     // 36864
#define STAGE_BYTES (A_BYTES + B_BYTES)         // 55296
#define BIAS_BYTE_OFF (NST * STAGE_BYTES)       // 165888
#define SMEM_BYTES (BIAS_BYTE_OFF + 1024)       // 166912
#define KTILES (KTOT / BK)                      // 68

__device__ __half g_Z[(size_t)MTOT * KTOT];
__device__ __half g_WB[(size_t)NTOT * KTOT];

__device__ __forceinline__ void cp16(void* sdst, const void* gsrc) {
    uint32_t s = (uint32_t)__cvta_generic_to_shared(sdst);
    asm volatile("cp.async.cg.shared.global [%0], [%1], 16;" :: "r"(s), "l"(gsrc));
}

__device__ __forceinline__ void ldsm4(uint32_t addr, uint32_t* r) {
    asm volatile("ldmatrix.sync.aligned.m8n8.x4.shared.b16 {%0,%1,%2,%3}, [%4];"
                 : "=r"(r[0]), "=r"(r[1]), "=r"(r[2]), "=r"(r[3]) : "r"(addr));
}

__device__ __forceinline__ float sigm(float v) { return 1.0f / (1.0f + __expf(-v)); }

// ---------------- convert kernels ----------------
__global__ __launch_bounds__(256) void conv_z(
    const float* __restrict__ x, const float* __restrict__ pt, const float* __restrict__ pl)
{
    int row = blockIdx.y;
    int c4 = blockIdx.x * 256 + threadIdx.x;
    if (c4 >= KTOT / 4) return;
    int col = c4 * 4;
    const float* src; int ld, cc;
    if (col < XDIM)             { src = x;  ld = XDIM; cc = col; }
    else if (col < XDIM + HDIM) { src = pt; ld = HDIM; cc = col - XDIM; }
    else                        { src = pl; ld = HDIM; cc = col - XDIM - HDIM; }
    float4 v = *reinterpret_cast<const float4*>(src + (size_t)row * ld + cc);
    __half2 h0 = __floats2half2_rn(v.x, v.y);
    __half2 h1 = __floats2half2_rn(v.z, v.w);
    uint2 u;
    u.x = *reinterpret_cast<uint32_t*>(&h0);
    u.y = *reinterpret_cast<uint32_t*>(&h1);
    *reinterpret_cast<uint2*>(g_Z + (size_t)row * KTOT + col) = u;
}

// gate interleave within 256-row CTA blocks: g = n_tile*256 + h_local*4 + gate
__global__ __launch_bounds__(256) void conv_w(
    const float* __restrict__ Wi, const float* __restrict__ Wf,
    const float* __restrict__ Wo, const float* __restrict__ Ws)
{
    int g = blockIdx.y;
    int c4 = blockIdx.x * 256 + threadIdx.x;
    if (c4 >= KTOT / 4) return;
    int n_tile = g >> 8, r = g & 255;
    int h = n_tile * 64 + (r >> 2);
    int gate = r & 3;
    const float* W = (gate == 0) ? Wi : (gate == 1) ? Wf : (gate == 2) ? Wo : Ws;
    int col = c4 * 4;
    float4 v = *reinterpret_cast<const float4*>(W + (size_t)h * KTOT + col);
    __half2 h0 = __floats2half2_rn(v.x, v.y);
    __half2 h1 = __floats2half2_rn(v.z, v.w);
    uint2 u;
    u.x = *reinterpret_cast<uint32_t*>(&h0);
    u.y = *reinterpret_cast<uint32_t*>(&h1);
    *reinterpret_cast<uint2*>(g_WB + (size_t)g * KTOT + col) = u;
}

__global__ void shim_kernel(void) {}

// ---------------- fp16 GEMM + fused LSTM: 128x256 CTA, 64x64 warp tiles ----------------
__global__ __launch_bounds__(256, 1) void gemm_lstm(
    const float* __restrict__ old_state,
    const float* __restrict__ bi, const float* __restrict__ bf,
    const float* __restrict__ bo, const float* __restrict__ bs,
    float* __restrict__ out)
{
    extern __shared__ __align__(16) char smem[];
    const uint32_t smem_u = (uint32_t)__cvta_generic_to_shared(smem);

    const int tid  = threadIdx.x;
    const int lane = tid & 31;
    const int warp = tid >> 5;
    const int wm   = (warp & 1) * 64;        // 2 warps in M
    const int wn   = (warp >> 1) * 64;       // 4 warps in N
    const int m0   = blockIdx.y * BM;
    const int n_tile = blockIdx.x;
    const int h0   = n_tile * 64;

    const __half* gA = g_Z  + (size_t)m0 * KTOT;
    const __half* gB = g_WB + (size_t)(n_tile * BN) * KTOT;

    float* bias_sm = reinterpret_cast<float*>(smem + BIAS_BYTE_OFF);   // [64][4]
    {
        int hl = tid >> 2, gate = tid & 3;
        const float* b = (gate == 0) ? bi : (gate == 1) ? bf : (gate == 2) ? bo : bs;
        bias_sm[tid] = b[h0 + hl];
    }

    // loader: rows of 128B = 8 chunks; 256 threads = 32 rows/iter
    const int lr = tid >> 3;
    const int lcb = (tid & 7) << 4;

    const uint32_t aOff = (uint32_t)((wm + (lane & 7) + ((lane >> 3) & 1) * 8) * ROWB
                                     + (lane >> 4) * 16);
    const uint32_t bOff = (uint32_t)(A_BYTES
                                     + (wn + (lane & 7) + ((lane >> 4) & 1) * 8) * ROWB
                                     + ((lane >> 3) & 1) * 16);

    float acc[4][8][4];
#pragma unroll
    for (int t = 0; t < 4; t++)
#pragma unroll
        for (int u = 0; u < 8; u++)
#pragma unroll
            for (int v = 0; v < 4; v++) acc[t][u][v] = 0.f;

    auto load_stage = [&](int kt) {
        char* As = smem + (kt % NST) * STAGE_BYTES;
        char* Bs = As + A_BYTES;
        const int k0 = kt * BK;
#pragma unroll
        for (int i = 0; i < 4; i++) {
            int r = lr + i * 32;
            cp16(As + r * ROWB + lcb, (const char*)(gA + (size_t)r * KTOT + k0) + lcb);
        }
#pragma unroll
        for (int i = 0; i < 8; i++) {
            int r = lr + i * 32;
            cp16(Bs + r * ROWB + lcb, (const char*)(gB + (size_t)r * KTOT + k0) + lcb);
        }
    };

#pragma unroll
    for (int s = 0; s < NST - 1; s++) {
        load_stage(s);
        asm volatile("cp.async.commit_group;");
    }

    uint32_t afr[2][4][4], bfr[2][4][4];

    for (int kt = 0; kt < KTILES; kt++) {
        asm volatile("cp.async.wait_group %0;" :: "n"(NST - 2));
        __syncthreads();

        const uint32_t stage = smem_u + (uint32_t)((kt % NST) * STAGE_BYTES);
        const uint32_t aBase = stage + aOff;
        const uint32_t bBase = stage + bOff;

        // prefetch ks=0 fragments
#pragma unroll
        for (int t = 0; t < 4; t++) ldsm4(aBase + t * (16 * ROWB), afr[0][t]);
#pragma unroll
        for (int j = 0; j < 4; j++) ldsm4(bBase + j * (16 * ROWB), bfr[0][j]);

        if (kt + NST - 1 < KTILES) load_stage(kt + NST - 1);
        asm volatile("cp.async.commit_group;");

#pragma unroll
        for (int ks = 0; ks < 4; ks++) {      // each ks = k16 (32B)
            const int cur = ks & 1, nxt = cur ^ 1;
            if (ks < 3) {
#pragma unroll
                for (int t = 0; t < 4; t++)
                    ldsm4(aBase + (ks + 1) * 32 + t * (16 * ROWB), afr[nxt][t]);
#pragma unroll
                for (int j = 0; j < 4; j++)
                    ldsm4(bBase + (ks + 1) * 32 + j * (16 * ROWB), bfr[nxt][j]);
            }
#pragma unroll
            for (int t = 0; t < 4; t++)
#pragma unroll
                for (int u = 0; u < 8; u++) {
                    const int j = u >> 1;
                    const uint32_t b0 = (u & 1) ? bfr[cur][j][2] : bfr[cur][j][0];
                    const uint32_t b1 = (u & 1) ? bfr[cur][j][3] : bfr[cur][j][1];
                    asm volatile(
                        "mma.sync.aligned.m16n8k16.row.col.f32.f16.f16.f32 "
                        "{%0,%1,%2,%3},{%4,%5,%6,%7},{%8,%9},{%0,%1,%2,%3};"
                        : "+f"(acc[t][u][0]), "+f"(acc[t][u][1]),
                          "+f"(acc[t][u][2]), "+f"(acc[t][u][3])
                        : "r"(afr[cur][t][0]), "r"(afr[cur][t][1]),
                          "r"(afr[cur][t][2]), "r"(afr[cur][t][3]),
                          "r"(b0), "r"(b1));
                }
        }
    }

    // ---- fused LSTM gate epilogue ----
    const int hadj = (lane & 3) >> 1;
    const int row_sel = (lane & 1) << 3;
#pragma unroll
    for (int t = 0; t < 4; t++) {
        int r_out = m0 + wm + t * 16 + (lane >> 2) + row_sel;
        const float* oldr = old_state + (size_t)r_out * HDIM + h0;
        float*       outr = out       + (size_t)r_out * HDIM + h0;
#pragma unroll
        for (int u = 0; u < 8; u++) {
            float v0 = acc[t][u][0], v1 = acc[t][u][1];
            float v2 = acc[t][u][2], v3 = acc[t][u][3];
            float t0 = (lane & 1) ? v0 : v2;
            float t1 = (lane & 1) ? v1 : v3;
            float e0 = __shfl_xor_sync(0xffffffffu, t0, 1);
            float e1 = __shfl_xor_sync(0xffffffffu, t1, 1);
            float gi, gf, go, gs;
            if (lane & 1) { gi = e0; gf = e1; go = v2; gs = v3; }
            else          { gi = v0; gf = v1; go = e0; gs = e1; }
            int hl = ((wn + u * 8) >> 2) + hadj;
            gi += bias_sm[hl * 4 + 0];
            gf += bias_sm[hl * 4 + 1];
            go += bias_sm[hl * 4 + 2];
            gs += bias_sm[hl * 4 + 3];
            float c  = __ldg(oldr + hl);
            float ns = sigm(gf) * c + sigm(gi) * tanhf(gs);
            outr[hl] = sigm(go) * tanhf(ns);
        }
    }
}

extern "C" void kernel_launch(void* const* d_in, const int* in_sizes, int n_in,
                              void* d_out, int out_size)
{
    const float* x  = (const float*)d_in[0];
    const float* pt = (const float*)d_in[1];
    const float* pl = (const float*)d_in[2];
    const float* os = (const float*)d_in[3];
    const float* Wi = (const float*)d_in[4];
    const float* bi = (const float*)d_in[5];
    const float* Wf = (const float*)d_in[6];
    const float* bf = (const float*)d_in[7];
    const float* Wo = (const float*)d_in[8];
    const float* bo = (const float*)d_in[9];
    const float* Ws = (const float*)d_in[10];
    const float* bs = (const float*)d_in[11];
    float* out = (float*)d_out;

    cudaFuncSetAttribute(gemm_lstm, cudaFuncAttributeMaxDynamicSharedMemorySize, SMEM_BYTES);

    conv_z<<<dim3(5, MTOT), 256>>>(x, pt, pl);
    conv_w<<<dim3(5, NTOT), 256>>>(Wi, Wf, Wo, Ws);
    shim_kernel<<<1, 32>>>();
    gemm_lstm<<<dim3(NTOT / BN, MTOT / BM), 256, SMEM_BYTES>>>(os, bi, bf, bo, bs, out);
}

// round 10
// speedup vs baseline: 1.8040x; 1.0025x over previous
#include <cuda_runtime.h>
#include <cuda_fp16.h>
#include <cstdint>
#include <cstddef>

#define MTOT 2048
#define NTOT 4096
#define KTOT 4352
#define HDIM 1024
#define XDIM 2304

#define BM 128
#define BN 256
#define BK 128                                  // halves per K-tile
#define ROWB 272                                // 256B data + 16B pad
#define A_BYTES (BM * ROWB)                     // 34816
#define B_BYTES (BN * ROWB)                     // 69632
#define STAGE_BYTES (A_BYTES + B_BYTES)         // 104448
#define BIAS_BYTE_OFF (2 * STAGE_BYTES)         // 208896
#define SMEM_BYTES (BIAS_BYTE_OFF + 1024)       // 209920
#define KTILES (KTOT / BK)                      // 34

__device__ __half g_Z[(size_t)MTOT * KTOT];
__device__ __half g_WB[(size_t)NTOT * KTOT];

__device__ __forceinline__ void cp16(void* sdst, const void* gsrc) {
    uint32_t s = (uint32_t)__cvta_generic_to_shared(sdst);
    asm volatile("cp.async.cg.shared.global [%0], [%1], 16;" :: "r"(s), "l"(gsrc));
}

__device__ __forceinline__ void ldsm4(uint32_t addr, uint32_t* r) {
    asm volatile("ldmatrix.sync.aligned.m8n8.x4.shared.b16 {%0,%1,%2,%3}, [%4];"
                 : "=r"(r[0]), "=r"(r[1]), "=r"(r[2]), "=r"(r[3]) : "r"(addr));
}

__device__ __forceinline__ float sigm(float v) { return 1.0f / (1.0f + __expf(-v)); }

// ---------------- merged convert kernel (Z rows then gate-interleaved W rows) ----------------
__global__ __launch_bounds__(256) void conv_all(
    const float* __restrict__ x, const float* __restrict__ pt, const float* __restrict__ pl,
    const float* __restrict__ Wi, const float* __restrict__ Wf,
    const float* __restrict__ Wo, const float* __restrict__ Ws)
{
    int y = blockIdx.y;
    int c4 = blockIdx.x * 256 + threadIdx.x;
    if (c4 >= KTOT / 4) return;
    int col = c4 * 4;

    const float* src;
    __half* dst;
    if (y < MTOT) {                       // Z row
        int cc;
        if (col < XDIM)             { src = x  + (size_t)y * XDIM; cc = col; }
        else if (col < XDIM + HDIM) { src = pt + (size_t)y * HDIM; cc = col - XDIM; }
        else                        { src = pl + (size_t)y * HDIM; cc = col - XDIM - HDIM; }
        src += cc - col;                  // so src[col] is right
        dst = g_Z + (size_t)y * KTOT;
    } else {                              // W row, gate-interleaved within 256-row blocks
        int g = y - MTOT;
        int n_tile = g >> 8, r = g & 255;
        int h = n_tile * 64 + (r >> 2);
        int gate = r & 3;
        const float* W = (gate == 0) ? Wi : (gate == 1) ? Wf : (gate == 2) ? Wo : Ws;
        src = W + (size_t)h * KTOT;
        dst = g_WB + (size_t)g * KTOT;
    }

    float4 v = *reinterpret_cast<const float4*>(src + col);
    __half2 h0 = __floats2half2_rn(v.x, v.y);
    __half2 h1 = __floats2half2_rn(v.z, v.w);
    uint2 u;
    u.x = *reinterpret_cast<uint32_t*>(&h0);
    u.y = *reinterpret_cast<uint32_t*>(&h1);
    *reinterpret_cast<uint2*>(dst + col) = u;
}

__global__ void shim_kernel(void) {}
__global__ void shim_kernel2(void) {}

// ---------------- fp16 GEMM + fused LSTM: 128x256 CTA, 64x64 warp tiles, BK=128 ----------------
__global__ __launch_bounds__(256, 1) void gemm_lstm(
    const float* __restrict__ old_state,
    const float* __restrict__ bi, const float* __restrict__ bf,
    const float* __restrict__ bo, const float* __restrict__ bs,
    float* __restrict__ out)
{
    extern __shared__ __align__(16) char smem[];
    const uint32_t smem_u = (uint32_t)__cvta_generic_to_shared(smem);

    const int tid  = threadIdx.x;
    const int lane = tid & 31;
    const int warp = tid >> 5;
    const int wm   = (warp & 1) * 64;
    const int wn   = (warp >> 1) * 64;
    const int m0   = blockIdx.y * BM;
    const int n_tile = blockIdx.x;
    const int h0   = n_tile * 64;

    const __half* gA = g_Z  + (size_t)m0 * KTOT;
    const __half* gB = g_WB + (size_t)(n_tile * BN) * KTOT;

    float* bias_sm = reinterpret_cast<float*>(smem + BIAS_BYTE_OFF);   // [64][4]
    {
        int hl = tid >> 2, gate = tid & 3;
        const float* b = (gate == 0) ? bi : (gate == 1) ? bf : (gate == 2) ? bo : bs;
        bias_sm[tid] = b[h0 + hl];
    }

    // loader: rows of 256B = 16 chunks; 256 threads = 16 rows/iter
    const int lr = tid >> 4;                 // 0..15
    const int lcb = (tid & 15) << 4;         // 0..240

    const uint32_t aOff = (uint32_t)((wm + (lane & 7) + ((lane >> 3) & 1) * 8) * ROWB
                                     + (lane >> 4) * 16);
    const uint32_t bOff = (uint32_t)(A_BYTES
                                     + (wn + (lane & 7) + ((lane >> 4) & 1) * 8) * ROWB
                                     + ((lane >> 3) & 1) * 16);

    float acc[4][8][4];
#pragma unroll
    for (int t = 0; t < 4; t++)
#pragma unroll
        for (int u = 0; u < 8; u++)
#pragma unroll
            for (int v = 0; v < 4; v++) acc[t][u][v] = 0.f;

    auto load_stage = [&](int kt) {
        char* As = smem + (kt & 1) * STAGE_BYTES;
        char* Bs = As + A_BYTES;
        const int k0 = kt * BK;
#pragma unroll
        for (int i = 0; i < 8; i++) {
            int r = lr + i * 16;
            cp16(As + r * ROWB + lcb, (const char*)(gA + (size_t)r * KTOT + k0) + lcb);
        }
#pragma unroll
        for (int i = 0; i < 16; i++) {
            int r = lr + i * 16;
            cp16(Bs + r * ROWB + lcb, (const char*)(gB + (size_t)r * KTOT + k0) + lcb);
        }
    };

    load_stage(0);
    asm volatile("cp.async.commit_group;");

    uint32_t afr[2][4][4], bfr[2][4][4];

    for (int kt = 0; kt < KTILES; kt++) {
        asm volatile("cp.async.wait_group 0;");
        __syncthreads();

        // next-stage load (slot (kt+1)&1 — its last readers finished before this barrier)
        if (kt + 1 < KTILES) {
            load_stage(kt + 1);
            asm volatile("cp.async.commit_group;");
        }

        const uint32_t stage = smem_u + (uint32_t)((kt & 1) * STAGE_BYTES);
        const uint32_t aBase = stage + aOff;
        const uint32_t bBase = stage + bOff;

        // prefetch ks=0 fragments
#pragma unroll
        for (int t = 0; t < 4; t++) ldsm4(aBase + t * (16 * ROWB), afr[0][t]);
#pragma unroll
        for (int j = 0; j < 4; j++) ldsm4(bBase + j * (16 * ROWB), bfr[0][j]);

#pragma unroll
        for (int ks = 0; ks < 8; ks++) {     // each ks = k16 (32B)
            const int cur = ks & 1, nxt = cur ^ 1;
            if (ks < 7) {
#pragma unroll
                for (int t = 0; t < 4; t++)
                    ldsm4(aBase + (ks + 1) * 32 + t * (16 * ROWB), afr[nxt][t]);
#pragma unroll
                for (int j = 0; j < 4; j++)
                    ldsm4(bBase + (ks + 1) * 32 + j * (16 * ROWB), bfr[nxt][j]);
            }
#pragma unroll
            for (int t = 0; t < 4; t++)
#pragma unroll
                for (int u = 0; u < 8; u++) {
                    const int j = u >> 1;
                    const uint32_t b0 = (u & 1) ? bfr[cur][j][2] : bfr[cur][j][0];
                    const uint32_t b1 = (u & 1) ? bfr[cur][j][3] : bfr[cur][j][1];
                    asm volatile(
                        "mma.sync.aligned.m16n8k16.row.col.f32.f16.f16.f32 "
                        "{%0,%1,%2,%3},{%4,%5,%6,%7},{%8,%9},{%0,%1,%2,%3};"
                        : "+f"(acc[t][u][0]), "+f"(acc[t][u][1]),
                          "+f"(acc[t][u][2]), "+f"(acc[t][u][3])
                        : "r"(afr[cur][t][0]), "r"(afr[cur][t][1]),
                          "r"(afr[cur][t][2]), "r"(afr[cur][t][3]),
                          "r"(b0), "r"(b1));
                }
        }
    }

    // ---- fused LSTM gate epilogue ----
    const int hadj = (lane & 3) >> 1;
    const int row_sel = (lane & 1) << 3;
#pragma unroll
    for (int t = 0; t < 4; t++) {
        int r_out = m0 + wm + t * 16 + (lane >> 2) + row_sel;
        const float* oldr = old_state + (size_t)r_out * HDIM + h0;
        float*       outr = out       + (size_t)r_out * HDIM + h0;
#pragma unroll
        for (int u = 0; u < 8; u++) {
            float v0 = acc[t][u][0], v1 = acc[t][u][1];
            float v2 = acc[t][u][2], v3 = acc[t][u][3];
            float t0 = (lane & 1) ? v0 : v2;
            float t1 = (lane & 1) ? v1 : v3;
            float e0 = __shfl_xor_sync(0xffffffffu, t0, 1);
            float e1 = __shfl_xor_sync(0xffffffffu, t1, 1);
            float gi, gf, go, gs;
            if (lane & 1) { gi = e0; gf = e1; go = v2; gs = v3; }
            else          { gi = v0; gf = v1; go = e0; gs = e1; }
            int hl = ((wn + u * 8) >> 2) + hadj;
            gi += bias_sm[hl * 4 + 0];
            gf += bias_sm[hl * 4 + 1];
            go += bias_sm[hl * 4 + 2];
            gs += bias_sm[hl * 4 + 3];
            float c  = __ldg(oldr + hl);
            float ns = sigm(gf) * c + sigm(gi) * tanhf(gs);
            outr[hl] = sigm(go) * tanhf(ns);
        }
    }
}

extern "C" void kernel_launch(void* const* d_in, const int* in_sizes, int n_in,
                              void* d_out, int out_size)
{
    const float* x  = (const float*)d_in[0];
    const float* pt = (const float*)d_in[1];
    const float* pl = (const float*)d_in[2];
    const float* os = (const float*)d_in[3];
    const float* Wi = (const float*)d_in[4];
    const float* bi = (const float*)d_in[5];
    const float* Wf = (const float*)d_in[6];
    const float* bf = (const float*)d_in[7];
    const float* Wo = (const float*)d_in[8];
    const float* bo = (const float*)d_in[9];
    const float* Ws = (const float*)d_in[10];
    const float* bs = (const float*)d_in[11];
    float* out = (float*)d_out;

    cudaFuncSetAttribute(gemm_lstm, cudaFuncAttributeMaxDynamicSharedMemorySize, SMEM_BYTES);

    conv_all<<<dim3(5, MTOT + NTOT), 256>>>(x, pt, pl, Wi, Wf, Wo, Ws);
    shim_kernel<<<1, 32>>>();
    shim_kernel2<<<1, 32>>>();
    gemm_lstm<<<dim3(NTOT / BN, MTOT / BM), 256, SMEM_BYTES>>>(os, bi, bf, bo, bs, out);
}